// round 5
// baseline (speedup 1.0000x reference)
#include <cuda_runtime.h>
#include <cuda_fp16.h>
#include <cstdint>

#define EPSV 1e-5f

// ---------------------------------------------------------------------------
// Scratch (fp16 stored as unsigned short)
// ---------------------------------------------------------------------------
__device__ unsigned short g_h  [4LL * 256 * 4096];   // h:   [c][n] per batch
__device__ unsigned short g_K  [4LL * 4096 * 256];   // Kt:  [n][ck]
__device__ unsigned short g_Q  [4LL * 4096 * 256];   // Qt:  [n][ck]
__device__ unsigned short g_V  [4LL * 256 * 4096];   // V:   [c][n]
__device__ unsigned short g_ctx[4LL * 256 * 4096];   // ctx: [c][n]
__device__ float          g_S  [4LL * 4096 * 4096];  // logits fp32
__device__ unsigned short g_P  [4LL * 4096 * 4096];  // probs fp16

__device__ __forceinline__ uint32_t pack_half2(float x, float y) {
    __half2 h = __floats2half2_rn(x, y);
    return *reinterpret_cast<uint32_t*>(&h);
}

__device__ __forceinline__ void mma_f16(float* d, const uint32_t* a, const uint32_t* b) {
    asm volatile(
        "mma.sync.aligned.m16n8k16.row.col.f32.f16.f16.f32 "
        "{%0,%1,%2,%3}, {%4,%5,%6,%7}, {%8,%9}, {%0,%1,%2,%3};"
        : "+f"(d[0]), "+f"(d[1]), "+f"(d[2]), "+f"(d[3])
        : "r"(a[0]), "r"(a[1]), "r"(a[2]), "r"(a[3]),
          "r"(b[0]), "r"(b[1]));
}

// ---------------------------------------------------------------------------
// Unified fp16 mma GEMM: D[m,n] = epi( sum_k A[m,k]*B[k,n] )
//  ASRC: 0 = A fp16 [M][K] (ldA, K contig); 1 = A fp32 [M][K]
//  BSRC: 0 = B fp16 [N][K] (B[n][k], K contig)
//        1 = B fp32 [K][N] (N contig)
//        2 = B fp16 [K][N] (N contig)
//  EPI : 0 = *scale; 1 = +bias[m]; 2 = relu((acc+bias[m])*s[m]+t[m])
//  OUT : 0 = fp32 C[m*ldC+n]; 1 = fp16 C[m*ldC+n]; 2 = fp16 C[n*ldC+m]
// CTA tile 128x128, BK=32 (2 ksteps of k16), 8 warps (2m x 4n), warp 64x32.
// SMEM: fragment-permuted fp16x2 words, double buffered.
//   per kstep: A 8 mfrags * 32 lanes * 4 words = 1024 (+8 pad) = 1032 words
//              B 16 nfrags * 32 lanes * 2 words = 1024 (+8 pad) = 1032 words
//   buffer = 2*1032 = 2064 words per operand; x2 buffers.
// Requires M%128==0, N%128==0, K%32==0.
// ---------------------------------------------------------------------------
template <int ASRC, int BSRC, int EPI, int OUT>
__global__ void __launch_bounds__(256, 2)
gemm_f16(const void* __restrict__ Av, long long sAb, int ldA,
         const void* __restrict__ Bv, long long sBb, int ldB,
         void* __restrict__ Cv, long long sCb, int ldC,
         int K, float scale,
         const float* __restrict__ bias,
         const float* __restrict__ gam, const float* __restrict__ bet,
         const float* __restrict__ mu,  const float* __restrict__ var)
{
    __shared__ uint32_t smw[8256];
    uint32_t* const Asm = smw;          // 2 x 2064 words
    uint32_t* const Bsm = smw + 4128;   // 2 x 2064 words

    const int tid = threadIdx.x, lane = tid & 31, wid = tid >> 5;
    const int wm = wid >> 2, wn = wid & 3;
    const int m0 = blockIdx.y * 128, n0 = blockIdx.x * 128;
    const long long bz = blockIdx.z;

    const __half* AgH = (const __half*)Av + bz * sAb + (long long)m0 * ldA;
    const float*  AgF = (const float* )Av + bz * sAb + (long long)m0 * ldA;
    const __half* BgN = (const __half*)Bv + bz * sBb + (long long)n0 * ldB;  // BSRC0
    const float*  BgKF = (const float*)Bv + bz * sBb + n0;                   // BSRC1
    const __half* BgKH = (const __half*)Bv + bz * sBb + n0;                  // BSRC2
    float*  CgF = (float*) Cv + bz * sCb;
    __half* CgH = (__half*)Cv + bz * sCb;

    // ---- staging metadata (chunk-invariant) ----
    int aoff[4], adst[4], aaux[4];
    int boff[4], bdst[4], baux[4];
    if (ASRC == 0) {
#pragma unroll
        for (int it = 0; it < 2; ++it) {
            int slot = it * 256 + tid, row = slot >> 2, kg = slot & 3;
            aoff[it] = row * ldA + kg * 8;
            adst[it] = (kg >> 1) * 1032 + (row >> 4) * 128 + (row & 7) * 16
                     + ((row >> 3) & 1) + 2 * (kg & 1);
            aaux[it] = (row >> 1) & 3;   // store rotation
        }
    } else {
#pragma unroll
        for (int it = 0; it < 4; ++it) {
            int slot = it * 256 + tid, row = slot >> 3, kg4 = slot & 7;
            int c = kg4 & 3;
            aoff[it] = row * ldA + kg4 * 4;
            adst[it] = (kg4 >> 2) * 1032 + (row >> 4) * 128 + (row & 7) * 16
                     + ((row >> 3) & 1) + 2 * (c >> 1);
            aaux[it] = (c & 1) * 2;      // t0
        }
    }
    if (BSRC == 0) {
#pragma unroll
        for (int it = 0; it < 2; ++it) {
            int slot = it * 256 + tid, row = slot >> 2, kg = slot & 3;
            boff[it] = row * ldB + kg * 8;
            bdst[it] = (kg >> 1) * 1032 + (row >> 3) * 64 + (row & 7) * 8 + (kg & 1);
            baux[it] = (row >> 1) & 3;
        }
    } else if (BSRC == 1) {
#pragma unroll
        for (int it = 0; it < 4; ++it) {
            int slot = it * 256 + tid, k = slot >> 5, nq = (slot & 31) * 4;
            int kk = k & 15, t = (kk >> 1) & 3, reg = kk >> 3, hb = k & 1;
            boff[it] = k * ldB + nq;
            bdst[it] = 2 * ((k >> 4) * 1032 + (nq >> 3) * 64 + (nq & 7) * 8
                            + 2 * t + reg) + hb;   // half index
        }
    } else {
#pragma unroll
        for (int it = 0; it < 2; ++it) {
            int slot = it * 256 + tid, k = slot >> 4, n8 = (slot & 15) * 8;
            int kk = k & 15, t = (kk >> 1) & 3, reg = kk >> 3, hb = k & 1;
            boff[it] = k * ldB + n8;
            bdst[it] = 2 * ((k >> 4) * 1032 + (n8 >> 3) * 64 + 2 * t + reg) + hb;
        }
    }
    const int NA = (ASRC == 0) ? 2 : 4;
    const int NB = (BSRC == 1) ? 4 : 2;

    float acc[4][4][4];
#pragma unroll
    for (int i = 0; i < 4; ++i)
#pragma unroll
        for (int j = 0; j < 4; ++j)
#pragma unroll
            for (int r = 0; r < 4; ++r) acc[i][j][r] = 0.f;

    const int NCH = K >> 5;

    // ---- store helpers (as macros via lambdas) ----
    auto storeA = [&](int buf, int it, const uint4& u) {
        uint32_t* W = Asm + buf * 2064 + adst[it];
        if (ASRC == 0) {
            uint32_t ua[4] = {u.x, u.y, u.z, u.w};
#pragma unroll
            for (int s = 0; s < 4; ++s) {
                int p = (s + aaux[it]) & 3;
                W[4 * p] = ua[p];
            }
        } else {
            const float4 v = *reinterpret_cast<const float4*>(&u);
            W[4 * aaux[it]]     = pack_half2(v.x, v.y);
            W[4 * aaux[it] + 4] = pack_half2(v.z, v.w);
        }
    };
    auto storeB = [&](int buf, int it, const uint4& u) {
        if (BSRC == 0) {
            uint32_t* W = Bsm + buf * 2064 + bdst[it];
            uint32_t ua[4] = {u.x, u.y, u.z, u.w};
#pragma unroll
            for (int s = 0; s < 4; ++s) {
                int p = (s + baux[it]) & 3;
                W[2 * p] = ua[p];
            }
        } else if (BSRC == 1) {
            const float4 v = *reinterpret_cast<const float4*>(&u);
            __half* Hb = (__half*)(Bsm + buf * 2064);
            Hb[bdst[it]]      = __float2half_rn(v.x);
            Hb[bdst[it] + 16] = __float2half_rn(v.y);
            Hb[bdst[it] + 32] = __float2half_rn(v.z);
            Hb[bdst[it] + 48] = __float2half_rn(v.w);
        } else {
            __half* Hb = (__half*)(Bsm + buf * 2064);
            const __half* src = reinterpret_cast<const __half*>(&u);
#pragma unroll
            for (int q = 0; q < 8; ++q)
                Hb[bdst[it] + 16 * q] = src[q];
        }
    };
    auto loadA = [&](int it, int k0) -> uint4 {
        if (ASRC == 0) return *reinterpret_cast<const uint4*>(AgH + aoff[it] + k0);
        else           return *reinterpret_cast<const uint4*>(AgF + aoff[it] + k0);
    };
    auto loadB = [&](int it, int k0) -> uint4 {
        if (BSRC == 0)      return *reinterpret_cast<const uint4*>(BgN  + boff[it] + k0);
        else if (BSRC == 1) return *reinterpret_cast<const uint4*>(BgKF + boff[it] + (long long)k0 * ldB);
        else                return *reinterpret_cast<const uint4*>(BgKH + boff[it] + (long long)k0 * ldB);
    };

    // ---- prologue: chunk 0 -> buffer 0 ----
#pragma unroll
    for (int it = 0; it < NA; ++it) storeA(0, it, loadA(it, 0));
#pragma unroll
    for (int it = 0; it < NB; ++it) storeB(0, it, loadB(it, 0));
    __syncthreads();

    for (int c = 0; c < NCH; ++c) {
        uint4 ra[4], rb[4];
        const bool pre = (c + 1 < NCH);
        if (pre) {
            const int k0 = (c + 1) << 5;
#pragma unroll
            for (int it = 0; it < NA; ++it) ra[it] = loadA(it, k0);
#pragma unroll
            for (int it = 0; it < NB; ++it) rb[it] = loadB(it, k0);
        }

        const uint32_t* Ab = Asm + (c & 1) * 2064;
        const uint32_t* Bb = Bsm + (c & 1) * 2064;
#pragma unroll
        for (int ks = 0; ks < 2; ++ks) {
            uint4 af[4];
            uint2 bf[4];
#pragma unroll
            for (int i = 0; i < 4; ++i)
                af[i] = *reinterpret_cast<const uint4*>(Ab + ks * 1032 + (wm * 4 + i) * 128 + lane * 4);
#pragma unroll
            for (int j = 0; j < 4; ++j)
                bf[j] = *reinterpret_cast<const uint2*>(Bb + ks * 1032 + (wn * 4 + j) * 64 + lane * 2);
#pragma unroll
            for (int i = 0; i < 4; ++i)
#pragma unroll
                for (int j = 0; j < 4; ++j)
                    mma_f16(acc[i][j], reinterpret_cast<const uint32_t*>(&af[i]),
                            reinterpret_cast<const uint32_t*>(&bf[j]));
        }

        if (pre) {
            const int nb = (c + 1) & 1;
#pragma unroll
            for (int it = 0; it < NA; ++it) storeA(nb, it, ra[it]);
#pragma unroll
            for (int it = 0; it < NB; ++it) storeB(nb, it, rb[it]);
        }
        __syncthreads();
    }

    // ---- epilogue ----
    const int g = lane >> 2, cq = lane & 3;
#pragma unroll
    for (int i = 0; i < 4; ++i) {
        const int mA = m0 + wm * 64 + i * 16 + g;
        const int mB = mA + 8;
        float bA = 0.f, bB = 0.f, sA = 1.f, sB = 1.f, tA = 0.f, tB = 0.f;
        if (EPI >= 1) { bA = bias[mA]; bB = bias[mB]; }
        if (EPI == 2) {
            sA = gam[mA] * rsqrtf(var[mA] + EPSV); tA = bet[mA] - mu[mA] * sA;
            sB = gam[mB] * rsqrtf(var[mB] + EPSV); tB = bet[mB] - mu[mB] * sB;
        }
#pragma unroll
        for (int j = 0; j < 4; ++j) {
            const int col = n0 + wn * 32 + j * 8 + cq * 2;
            float v00 = acc[i][j][0], v01 = acc[i][j][1];
            float v10 = acc[i][j][2], v11 = acc[i][j][3];
            if (EPI == 0) { v00 *= scale; v01 *= scale; v10 *= scale; v11 *= scale; }
            if (EPI == 1) { v00 += bA; v01 += bA; v10 += bB; v11 += bB; }
            if (EPI == 2) {
                v00 = fmaxf(fmaf(v00 + bA, sA, tA), 0.f);
                v01 = fmaxf(fmaf(v01 + bA, sA, tA), 0.f);
                v10 = fmaxf(fmaf(v10 + bB, sB, tB), 0.f);
                v11 = fmaxf(fmaf(v11 + bB, sB, tB), 0.f);
            }
            if (OUT == 0) {
                *(float2*)&CgF[(long long)mA * ldC + col] = make_float2(v00, v01);
                *(float2*)&CgF[(long long)mB * ldC + col] = make_float2(v10, v11);
            } else if (OUT == 1) {
                *(__half2*)&CgH[(long long)mA * ldC + col] = __floats2half2_rn(v00, v01);
                *(__half2*)&CgH[(long long)mB * ldC + col] = __floats2half2_rn(v10, v11);
            } else {
                CgH[(long long)col * ldC + mA]       = __float2half_rn(v00);
                CgH[(long long)(col + 1) * ldC + mA] = __float2half_rn(v01);
                CgH[(long long)col * ldC + mB]       = __float2half_rn(v10);
                CgH[(long long)(col + 1) * ldC + mB] = __float2half_rn(v11);
            }
        }
    }
}

// ---------------------------------------------------------------------------
// Row softmax: S fp32 [row][4096] -> P fp16, one 256-thread block per row.
// ---------------------------------------------------------------------------
__global__ void __launch_bounds__(256)
softmax_kernel(const float* __restrict__ S, __half* __restrict__ P)
{
    const int N = 4096;
    const float* p = S + (long long)blockIdx.x * N;
    __half* po = P + (long long)blockIdx.x * N;
    const int tid = threadIdx.x;

    float4 v[4];
    float mx = -3.4e38f;
#pragma unroll
    for (int i = 0; i < 4; i++) {
        v[i] = *(const float4*)&p[i * 1024 + tid * 4];
        mx = fmaxf(mx, fmaxf(fmaxf(v[i].x, v[i].y), fmaxf(v[i].z, v[i].w)));
    }

    __shared__ float redA[8];
    __shared__ float redB[8];
#pragma unroll
    for (int o = 16; o; o >>= 1)
        mx = fmaxf(mx, __shfl_xor_sync(0xffffffffu, mx, o));
    if ((tid & 31) == 0) redA[tid >> 5] = mx;
    __syncthreads();
#pragma unroll
    for (int w = 0; w < 8; w++) mx = fmaxf(mx, redA[w]);

    float sum = 0.f;
#pragma unroll
    for (int i = 0; i < 4; i++) {
        v[i].x = __expf(v[i].x - mx);
        v[i].y = __expf(v[i].y - mx);
        v[i].z = __expf(v[i].z - mx);
        v[i].w = __expf(v[i].w - mx);
        sum += v[i].x + v[i].y + v[i].z + v[i].w;
    }
#pragma unroll
    for (int o = 16; o; o >>= 1)
        sum += __shfl_xor_sync(0xffffffffu, sum, o);
    if ((tid & 31) == 0) redB[tid >> 5] = sum;
    __syncthreads();
    sum = 0.f;
#pragma unroll
    for (int w = 0; w < 8; w++) sum += redB[w];

    const float inv = 1.f / sum;
#pragma unroll
    for (int i = 0; i < 4; i++) {
        __half2* q = (__half2*)&po[i * 1024 + tid * 4];
        q[0] = __floats2half2_rn(v[i].x * inv, v[i].y * inv);
        q[1] = __floats2half2_rn(v[i].z * inv, v[i].w * inv);
    }
}

// ---------------------------------------------------------------------------
extern "C" void kernel_launch(void* const* d_in, const int* in_sizes, int n_in,
                              void* d_out, int out_size)
{
    const float* x     = (const float*)d_in[0];
    const float* k_w1  = (const float*)d_in[1];
    const float* k_b1  = (const float*)d_in[2];
    const float* k_g1  = (const float*)d_in[3];
    const float* k_be1 = (const float*)d_in[4];
    const float* k_m1  = (const float*)d_in[5];
    const float* k_v1  = (const float*)d_in[6];
    const float* k_w2  = (const float*)d_in[7];
    const float* k_b2  = (const float*)d_in[8];
    const float* k_g2  = (const float*)d_in[9];
    const float* k_be2 = (const float*)d_in[10];
    const float* k_m2  = (const float*)d_in[11];
    const float* k_v2  = (const float*)d_in[12];
    const float* q_w1  = (const float*)d_in[13];
    const float* q_b1  = (const float*)d_in[14];
    const float* q_g1  = (const float*)d_in[15];
    const float* q_be1 = (const float*)d_in[16];
    const float* q_m1  = (const float*)d_in[17];
    const float* q_v1  = (const float*)d_in[18];
    const float* q_w2  = (const float*)d_in[19];
    const float* q_b2  = (const float*)d_in[20];
    const float* q_g2  = (const float*)d_in[21];
    const float* q_be2 = (const float*)d_in[22];
    const float* q_m2  = (const float*)d_in[23];
    const float* q_v2  = (const float*)d_in[24];
    const float* v_w   = (const float*)d_in[25];
    const float* v_b   = (const float*)d_in[26];
    const float* o_w   = (const float*)d_in[27];
    const float* o_b   = (const float*)d_in[28];

    void *h, *Kt, *Qt, *Vf, *S, *P, *ctx;
    cudaGetSymbolAddress(&h,   g_h);
    cudaGetSymbolAddress(&Kt,  g_K);
    cudaGetSymbolAddress(&Qt,  g_Q);
    cudaGetSymbolAddress(&Vf,  g_V);
    cudaGetSymbolAddress(&S,   g_S);
    cudaGetSymbolAddress(&P,   g_P);
    cudaGetSymbolAddress(&ctx, g_ctx);

    const long long sX = 512LL * 4096;   // x per batch (fp32)
    const long long sC = 256LL * 4096;   // 256-ch fp16 maps / Kt,Qt
    const long long sS = 4096LL * 4096;  // attention per batch
    const long long sO = 512LL * 4096;   // output per batch

    const dim3 gProj(32, 2, 4);
    const dim3 gOut (32, 4, 4);
    const dim3 gSim (32, 32, 4);

    // ---- k branch ----
    gemm_f16<1, 1, 2, 1><<<gProj, 256>>>(k_w1, 0, 512, x, sX, 4096, h, sC, 4096,
                                         512, 0.f, k_b1, k_g1, k_be1, k_m1, k_v1);
    gemm_f16<1, 2, 2, 2><<<gProj, 256>>>(k_w2, 0, 256, h, sC, 4096, Kt, sC, 256,
                                         256, 0.f, k_b2, k_g2, k_be2, k_m2, k_v2);
    // ---- q branch ----
    gemm_f16<1, 1, 2, 1><<<gProj, 256>>>(q_w1, 0, 512, x, sX, 4096, h, sC, 4096,
                                         512, 0.f, q_b1, q_g1, q_be1, q_m1, q_v1);
    gemm_f16<1, 2, 2, 2><<<gProj, 256>>>(q_w2, 0, 256, h, sC, 4096, Qt, sC, 256,
                                         256, 0.f, q_b2, q_g2, q_be2, q_m2, q_v2);
    // ---- value ----
    gemm_f16<1, 1, 1, 1><<<gProj, 256>>>(v_w, 0, 512, x, sX, 4096, Vf, sC, 4096,
                                         512, 0.f, v_b, nullptr, nullptr, nullptr, nullptr);
    // ---- sim[nq,nk] = 0.0625 * <Qt[nq,:], Kt[nk,:]> ----
    gemm_f16<0, 0, 0, 0><<<gSim, 256>>>(Qt, sC, 256, Kt, sC, 256, S, sS, 4096,
                                        256, 0.0625f, nullptr, nullptr, nullptr, nullptr, nullptr);
    // ---- softmax over keys, fp16 out ----
    softmax_kernel<<<4 * 4096, 256>>>((const float*)S, (__half*)P);
    // ---- ctx[c,nq] = sum_m V[c,m] * P[nq,m] ----
    gemm_f16<0, 0, 0, 1><<<gProj, 256>>>(Vf, sC, 4096, P, sS, 4096, ctx, sC, 4096,
                                         4096, 1.0f, nullptr, nullptr, nullptr, nullptr, nullptr);
    // ---- out = Wo ctx + bo ----
    gemm_f16<1, 2, 1, 0><<<gOut, 256>>>(o_w, 0, 256, ctx, sC, 4096, d_out, sO, 4096,
                                        256, 0.f, o_b, nullptr, nullptr, nullptr, nullptr);
}

// round 6
// speedup vs baseline: 1.2230x; 1.2230x over previous
#include <cuda_runtime.h>
#include <cuda_fp16.h>
#include <cstdint>

#define EPSV 1e-5f

// ---------------------------------------------------------------------------
// Scratch
// ---------------------------------------------------------------------------
__device__ __align__(16) __half g_xT [4LL * 4096 * 512];   // xT: [b][n][c] fp16
__device__ __align__(16) __half g_wh [655360];             // converted weights
__device__ __align__(16) __half g_h  [4LL * 4096 * 256];   // h:   [n][c]
__device__ __align__(16) __half g_K  [4LL * 4096 * 256];   // Kt:  [n][ck]
__device__ __align__(16) __half g_Q  [4LL * 4096 * 256];   // Qt:  [n][ck]
__device__ __align__(16) __half g_V  [4LL * 256 * 4096];   // V:   [c][n]
__device__ __align__(16) __half g_ctx[4LL * 4096 * 256];   // ctxT:[n][c]
__device__ float               g_S  [4LL * 4096 * 4096];   // logits fp32
__device__ __align__(16) __half g_P  [4LL * 4096 * 4096];  // probs fp16

// weight offsets inside g_wh
#define W_KW1 0
#define W_KW2 131072
#define W_QW1 196608
#define W_QW2 327680
#define W_VW  393216
#define W_OW  524288

// ---------------------------------------------------------------------------
// PTX helpers (all sm_80/75-era -- safe under plain sm_103 ptx target)
// ---------------------------------------------------------------------------
__device__ __forceinline__ uint32_t smem_u32(const void* p) {
    uint32_t a;
    asm("{ .reg .u64 t; cvta.to.shared.u64 t, %1; cvt.u32.u64 %0, t; }" : "=r"(a) : "l"(p));
    return a;
}
#define CP_ASYNC16(dst, src) \
    asm volatile("cp.async.cg.shared.global [%0], [%1], 16;" :: "r"(dst), "l"(src))
#define CP_COMMIT() asm volatile("cp.async.commit_group;" ::: "memory")
#define CP_WAIT2()  asm volatile("cp.async.wait_group 2;"  ::: "memory")

__device__ __forceinline__ void ldsm_x4(uint32_t& r0, uint32_t& r1, uint32_t& r2,
                                        uint32_t& r3, uint32_t addr) {
    asm volatile("ldmatrix.sync.aligned.m8n8.x4.shared.b16 {%0,%1,%2,%3}, [%4];"
                 : "=r"(r0), "=r"(r1), "=r"(r2), "=r"(r3) : "r"(addr));
}
__device__ __forceinline__ void mma_f16(float* d, const uint32_t* a, const uint32_t* b) {
    asm volatile(
        "mma.sync.aligned.m16n8k16.row.col.f32.f16.f16.f32 "
        "{%0,%1,%2,%3}, {%4,%5,%6,%7}, {%8,%9}, {%0,%1,%2,%3};"
        : "+f"(d[0]), "+f"(d[1]), "+f"(d[2]), "+f"(d[3])
        : "r"(a[0]), "r"(a[1]), "r"(a[2]), "r"(a[3]),
          "r"(b[0]), "r"(b[1]));
}

// ---------------------------------------------------------------------------
// Preprocessing: fp32 -> fp16 convert, and transpose-convert of x
// ---------------------------------------------------------------------------
__global__ void f2h_kernel(const float* __restrict__ s, __half* __restrict__ d, int n)
{
    int i = (blockIdx.x * blockDim.x + threadIdx.x) * 4;
    if (i < n) {
        float4 v = *(const float4*)(s + i);
        *(__half2*)(d + i)     = __floats2half2_rn(v.x, v.y);
        *(__half2*)(d + i + 2) = __floats2half2_rn(v.z, v.w);
    }
}

// x [4][512][4096] fp32 -> xT [4][4096][512] fp16
__global__ void xT_kernel(const float* __restrict__ x, __half* __restrict__ xT)
{
    __shared__ float t[32][33];
    const int n0 = blockIdx.x * 32, c0 = blockIdx.y * 32;
    const long long b = blockIdx.z;
    const float* xb = x + (b * 512 + c0) * 4096 + n0;
#pragma unroll
    for (int j = 0; j < 32; j += 8)
        t[threadIdx.y + j][threadIdx.x] = xb[(long long)(threadIdx.y + j) * 4096 + threadIdx.x];
    __syncthreads();
    __half* dst = xT + (b * 4096 + n0) * 512 + c0;
#pragma unroll
    for (int j = 0; j < 32; j += 8)
        dst[(long long)(threadIdx.y + j) * 512 + threadIdx.x] =
            __float2half_rn(t[threadIdx.x][threadIdx.y + j]);
}

// ---------------------------------------------------------------------------
// fp16 GEMM: D[m,n] = epi( sum_k A[m,k]*B[n,k] )
// A fp16 [M][K] (ldA, K contig), B fp16 [N][K] (ldB, K contig).
// CTA 128x128, BK=32, 4-stage cp.async pipeline, ldmatrix fragments.
// 8 warps (2m x 4n), warp tile 64x32.
//  EPI: 0 = *scale; 1 = +bias[m]; 2 = relu((acc+bias[m])*s[m]+t[m])
//  OUT: 0 = fp32 C[m*ldC+n]; 1 = fp16 C[m*ldC+n]; 2 = fp16 C[n*ldC+m]
// SMEM per stage: A 128 rows x 80B + B same = 20480B; 4 stages = 81920B.
// ---------------------------------------------------------------------------
template <int EPI, int OUT>
__global__ void __launch_bounds__(256, 2)
gemm16(const __half* __restrict__ A, long long sAb, int ldA,
       const __half* __restrict__ B, long long sBb, int ldB,
       void* __restrict__ Cv, long long sCb, int ldC,
       int K, float scale,
       const float* __restrict__ bias,
       const float* __restrict__ gam, const float* __restrict__ bet,
       const float* __restrict__ mu,  const float* __restrict__ var)
{
    extern __shared__ char sm[];
    const uint32_t sb = smem_u32(sm);

    const int tid = threadIdx.x, lane = tid & 31, wid = tid >> 5;
    const int wm = wid >> 2, wn = wid & 3;
    const int m0 = blockIdx.y * 128, n0 = blockIdx.x * 128;
    const long long bz = blockIdx.z;

    A += bz * sAb + (long long)m0 * ldA;
    B += bz * sBb + (long long)n0 * ldB;

    const int crow = tid >> 2;        // 0..63
    const int cq   = tid & 3;         // quad within row

    auto issue = [&](int s, int c) {
        const int k0 = c << 5;
        const uint32_t st = sb + s * 20480;
#pragma unroll
        for (int i = 0; i < 2; ++i) {
            const int row = i * 64 + crow;
            CP_ASYNC16(st + row * 80 + cq * 16,
                       A + (long long)row * ldA + k0 + cq * 8);
            CP_ASYNC16(st + 10240 + row * 80 + cq * 16,
                       B + (long long)row * ldB + k0 + cq * 8);
        }
    };

    float acc[4][4][4];
#pragma unroll
    for (int i = 0; i < 4; ++i)
#pragma unroll
        for (int j = 0; j < 4; ++j)
#pragma unroll
            for (int r = 0; r < 4; ++r) acc[i][j][r] = 0.f;

    const int NCH = K >> 5;

    issue(0, 0); CP_COMMIT();
    issue(1, 1); CP_COMMIT();
    issue(2, 2); CP_COMMIT();

    // fragment smem offsets (stage-invariant parts)
    const uint32_t aoff = (wm * 64 + (lane & 15)) * 80 + (lane >> 4) * 16;
    const uint32_t boff = 10240 + (wn * 32 + (lane & 7) + ((lane >> 4) << 3)) * 80
                        + ((lane >> 3) & 1) * 16;

    for (int c = 0; c < NCH; ++c) {
        CP_WAIT2();
        __syncthreads();
        const uint32_t st = sb + (c & 3) * 20480;

        uint32_t a0[4][4], b0[4][2];
        // ---- kstep 0 loads ----
#pragma unroll
        for (int i = 0; i < 4; ++i)
            ldsm_x4(a0[i][0], a0[i][1], a0[i][2], a0[i][3],
                    st + aoff + i * (16 * 80));
#pragma unroll
        for (int p = 0; p < 2; ++p) {
            uint32_t t0, t1, t2, t3;
            ldsm_x4(t0, t1, t2, t3, st + boff + p * (16 * 80));
            b0[2 * p][0] = t0; b0[2 * p][1] = t1;
            b0[2 * p + 1][0] = t2; b0[2 * p + 1][1] = t3;
        }

        // ---- prefetch next stage ----
        if (c + 3 < NCH) issue((c + 3) & 3, c + 3);
        CP_COMMIT();

        // ---- kstep 0 mma ----
#pragma unroll
        for (int i = 0; i < 4; ++i)
#pragma unroll
            for (int j = 0; j < 4; ++j)
                mma_f16(acc[i][j], a0[i], b0[j]);

        // ---- kstep 1 loads + mma ----
        uint32_t a1[4][4], b1[4][2];
#pragma unroll
        for (int i = 0; i < 4; ++i)
            ldsm_x4(a1[i][0], a1[i][1], a1[i][2], a1[i][3],
                    st + aoff + i * (16 * 80) + 32);
#pragma unroll
        for (int p = 0; p < 2; ++p) {
            uint32_t t0, t1, t2, t3;
            ldsm_x4(t0, t1, t2, t3, st + boff + p * (16 * 80) + 32);
            b1[2 * p][0] = t0; b1[2 * p][1] = t1;
            b1[2 * p + 1][0] = t2; b1[2 * p + 1][1] = t3;
        }
#pragma unroll
        for (int i = 0; i < 4; ++i)
#pragma unroll
            for (int j = 0; j < 4; ++j)
                mma_f16(acc[i][j], a1[i], b1[j]);
    }

    // ---- epilogue ----
    float*  CgF = (float*) Cv + bz * sCb;
    __half* CgH = (__half*)Cv + bz * sCb;
    const int g = lane >> 2, q4 = lane & 3;
#pragma unroll
    for (int i = 0; i < 4; ++i) {
        const int mA = m0 + wm * 64 + i * 16 + g;
        const int mB = mA + 8;
        float bA = 0.f, bB = 0.f, sA = 1.f, sB = 1.f, tA = 0.f, tB = 0.f;
        if (EPI >= 1) { bA = bias[mA]; bB = bias[mB]; }
        if (EPI == 2) {
            sA = gam[mA] * rsqrtf(var[mA] + EPSV); tA = bet[mA] - mu[mA] * sA;
            sB = gam[mB] * rsqrtf(var[mB] + EPSV); tB = bet[mB] - mu[mB] * sB;
        }
#pragma unroll
        for (int j = 0; j < 4; ++j) {
            const int col = n0 + wn * 32 + j * 8 + q4 * 2;
            float v00 = acc[i][j][0], v01 = acc[i][j][1];
            float v10 = acc[i][j][2], v11 = acc[i][j][3];
            if (EPI == 0) { v00 *= scale; v01 *= scale; v10 *= scale; v11 *= scale; }
            if (EPI == 1) { v00 += bA; v01 += bA; v10 += bB; v11 += bB; }
            if (EPI == 2) {
                v00 = fmaxf(fmaf(v00 + bA, sA, tA), 0.f);
                v01 = fmaxf(fmaf(v01 + bA, sA, tA), 0.f);
                v10 = fmaxf(fmaf(v10 + bB, sB, tB), 0.f);
                v11 = fmaxf(fmaf(v11 + bB, sB, tB), 0.f);
            }
            if (OUT == 0) {
                *(float2*)&CgF[(long long)mA * ldC + col] = make_float2(v00, v01);
                *(float2*)&CgF[(long long)mB * ldC + col] = make_float2(v10, v11);
            } else if (OUT == 1) {
                *(__half2*)&CgH[(long long)mA * ldC + col] = __floats2half2_rn(v00, v01);
                *(__half2*)&CgH[(long long)mB * ldC + col] = __floats2half2_rn(v10, v11);
            } else {
                CgH[(long long)col * ldC + mA]       = __float2half_rn(v00);
                CgH[(long long)(col + 1) * ldC + mA] = __float2half_rn(v01);
                CgH[(long long)col * ldC + mB]       = __float2half_rn(v10);
                CgH[(long long)(col + 1) * ldC + mB] = __float2half_rn(v11);
            }
        }
    }
}

// ---------------------------------------------------------------------------
// Row softmax: S fp32 [row][4096] -> P fp16, one 256-thread block per row.
// ---------------------------------------------------------------------------
__global__ void __launch_bounds__(256)
softmax_kernel(const float* __restrict__ S, __half* __restrict__ P)
{
    const int N = 4096;
    const float* p = S + (long long)blockIdx.x * N;
    __half* po = P + (long long)blockIdx.x * N;
    const int tid = threadIdx.x;

    float4 v[4];
    float mx = -3.4e38f;
#pragma unroll
    for (int i = 0; i < 4; i++) {
        v[i] = *(const float4*)&p[i * 1024 + tid * 4];
        mx = fmaxf(mx, fmaxf(fmaxf(v[i].x, v[i].y), fmaxf(v[i].z, v[i].w)));
    }

    __shared__ float redA[8];
    __shared__ float redB[8];
#pragma unroll
    for (int o = 16; o; o >>= 1)
        mx = fmaxf(mx, __shfl_xor_sync(0xffffffffu, mx, o));
    if ((tid & 31) == 0) redA[tid >> 5] = mx;
    __syncthreads();
#pragma unroll
    for (int w = 0; w < 8; w++) mx = fmaxf(mx, redA[w]);

    float sum = 0.f;
#pragma unroll
    for (int i = 0; i < 4; i++) {
        v[i].x = __expf(v[i].x - mx);
        v[i].y = __expf(v[i].y - mx);
        v[i].z = __expf(v[i].z - mx);
        v[i].w = __expf(v[i].w - mx);
        sum += v[i].x + v[i].y + v[i].z + v[i].w;
    }
#pragma unroll
    for (int o = 16; o; o >>= 1)
        sum += __shfl_xor_sync(0xffffffffu, sum, o);
    if ((tid & 31) == 0) redB[tid >> 5] = sum;
    __syncthreads();
    sum = 0.f;
#pragma unroll
    for (int w = 0; w < 8; w++) sum += redB[w];

    const float inv = 1.f / sum;
#pragma unroll
    for (int i = 0; i < 4; i++) {
        __half2* q = (__half2*)&po[i * 1024 + tid * 4];
        q[0] = __floats2half2_rn(v[i].x * inv, v[i].y * inv);
        q[1] = __floats2half2_rn(v[i].z * inv, v[i].w * inv);
    }
}

// ---------------------------------------------------------------------------
extern "C" void kernel_launch(void* const* d_in, const int* in_sizes, int n_in,
                              void* d_out, int out_size)
{
    const float* x     = (const float*)d_in[0];
    const float* k_w1  = (const float*)d_in[1];
    const float* k_b1  = (const float*)d_in[2];
    const float* k_g1  = (const float*)d_in[3];
    const float* k_be1 = (const float*)d_in[4];
    const float* k_m1  = (const float*)d_in[5];
    const float* k_v1  = (const float*)d_in[6];
    const float* k_w2  = (const float*)d_in[7];
    const float* k_b2  = (const float*)d_in[8];
    const float* k_g2  = (const float*)d_in[9];
    const float* k_be2 = (const float*)d_in[10];
    const float* k_m2  = (const float*)d_in[11];
    const float* k_v2  = (const float*)d_in[12];
    const float* q_w1  = (const float*)d_in[13];
    const float* q_b1  = (const float*)d_in[14];
    const float* q_g1  = (const float*)d_in[15];
    const float* q_be1 = (const float*)d_in[16];
    const float* q_m1  = (const float*)d_in[17];
    const float* q_v1  = (const float*)d_in[18];
    const float* q_w2  = (const float*)d_in[19];
    const float* q_b2  = (const float*)d_in[20];
    const float* q_g2  = (const float*)d_in[21];
    const float* q_be2 = (const float*)d_in[22];
    const float* q_m2  = (const float*)d_in[23];
    const float* q_v2  = (const float*)d_in[24];
    const float* v_w   = (const float*)d_in[25];
    const float* v_b   = (const float*)d_in[26];
    const float* o_w   = (const float*)d_in[27];
    const float* o_b   = (const float*)d_in[28];

    void *xT_, *wh_, *h_, *Kt_, *Qt_, *V_, *S_, *P_, *ctx_;
    cudaGetSymbolAddress(&xT_,  g_xT);
    cudaGetSymbolAddress(&wh_,  g_wh);
    cudaGetSymbolAddress(&h_,   g_h);
    cudaGetSymbolAddress(&Kt_,  g_K);
    cudaGetSymbolAddress(&Qt_,  g_Q);
    cudaGetSymbolAddress(&V_,   g_V);
    cudaGetSymbolAddress(&S_,   g_S);
    cudaGetSymbolAddress(&P_,   g_P);
    cudaGetSymbolAddress(&ctx_, g_ctx);
    __half* xT  = (__half*)xT_;
    __half* wh  = (__half*)wh_;
    __half* h   = (__half*)h_;
    __half* Kt  = (__half*)Kt_;
    __half* Qt  = (__half*)Qt_;
    __half* V   = (__half*)V_;
    float*  S   = (float*)S_;
    __half* P   = (__half*)P_;
    __half* ctx = (__half*)ctx_;

    const long long sXT = 4096LL * 512;
    const long long sC  = 4096LL * 256;
    const long long sS  = 4096LL * 4096;
    const long long sO  = 512LL * 4096;

    const int GSM = 81920;
    cudaFuncSetAttribute(gemm16<2,2>, cudaFuncAttributeMaxDynamicSharedMemorySize, GSM);
    cudaFuncSetAttribute(gemm16<1,1>, cudaFuncAttributeMaxDynamicSharedMemorySize, GSM);
    cudaFuncSetAttribute(gemm16<0,0>, cudaFuncAttributeMaxDynamicSharedMemorySize, GSM);
    cudaFuncSetAttribute(gemm16<0,2>, cudaFuncAttributeMaxDynamicSharedMemorySize, GSM);
    cudaFuncSetAttribute(gemm16<1,0>, cudaFuncAttributeMaxDynamicSharedMemorySize, GSM);

    // ---- preprocessing ----
    f2h_kernel<<<128, 256>>>(k_w1, wh + W_KW1, 131072);
    f2h_kernel<<< 64, 256>>>(k_w2, wh + W_KW2,  65536);
    f2h_kernel<<<128, 256>>>(q_w1, wh + W_QW1, 131072);
    f2h_kernel<<< 64, 256>>>(q_w2, wh + W_QW2,  65536);
    f2h_kernel<<<128, 256>>>(v_w,  wh + W_VW,  131072);
    f2h_kernel<<<128, 256>>>(o_w,  wh + W_OW,  131072);
    xT_kernel<<<dim3(128, 16, 4), dim3(32, 8)>>>(x, xT);

    const dim3 gProj(32, 2, 4);   // M=256
    const dim3 gOut (32, 4, 4);   // M=512
    const dim3 gSim (32, 32, 4);

    // ---- k branch: h[n][c] = relu(bn(W1 x)); Kt[n][ck] = relu(bn(W2 h)) ----
    gemm16<2,2><<<gProj, 256, GSM>>>(wh + W_KW1, 0, 512, xT, sXT, 512, h, sC, 256,
                                     512, 0.f, k_b1, k_g1, k_be1, k_m1, k_v1);
    gemm16<2,2><<<gProj, 256, GSM>>>(wh + W_KW2, 0, 256, h, sC, 256, Kt, sC, 256,
                                     256, 0.f, k_b2, k_g2, k_be2, k_m2, k_v2);
    // ---- q branch ----
    gemm16<2,2><<<gProj, 256, GSM>>>(wh + W_QW1, 0, 512, xT, sXT, 512, h, sC, 256,
                                     512, 0.f, q_b1, q_g1, q_be1, q_m1, q_v1);
    gemm16<2,2><<<gProj, 256, GSM>>>(wh + W_QW2, 0, 256, h, sC, 256, Qt, sC, 256,
                                     256, 0.f, q_b2, q_g2, q_be2, q_m2, q_v2);
    // ---- value: V[c][n] ----
    gemm16<1,1><<<gProj, 256, GSM>>>(wh + W_VW, 0, 512, xT, sXT, 512, V, sC, 4096,
                                     512, 0.f, v_b, nullptr, nullptr, nullptr, nullptr);
    // ---- sim[nq][nk] = 0.0625 * <Qt[nq,:], Kt[nk,:]> (fp32 out) ----
    gemm16<0,0><<<gSim, 256, GSM>>>(Qt, sC, 256, Kt, sC, 256, S, sS, 4096,
                                    256, 0.0625f, nullptr, nullptr, nullptr, nullptr, nullptr);
    // ---- softmax over keys ----
    softmax_kernel<<<4 * 4096, 256>>>(S, P);
    // ---- ctxT[nq][c] = sum_key V[c,key] * P[nq,key] ----
    gemm16<0,2><<<gProj, 256, GSM>>>(V, sC, 4096, P, sS, 4096, ctx, sC, 256,
                                     4096, 1.0f, nullptr, nullptr, nullptr, nullptr, nullptr);
    // ---- out[co][n] = o_w @ ctx + o_b (fp32) ----
    gemm16<1,0><<<gOut, 256, GSM>>>(wh + W_OW, 0, 256, ctx, sC, 256, d_out, sO, 4096,
                                    256, 0.f, o_b, nullptr, nullptr, nullptr, nullptr);
}

// round 7
// speedup vs baseline: 1.7948x; 1.4676x over previous
#include <cuda_runtime.h>
#include <cuda_fp16.h>
#include <cstdint>

#define EPSV 1e-5f

// ---------------------------------------------------------------------------
// Scratch
// ---------------------------------------------------------------------------
__device__ __align__(16) __half g_xT [4LL * 4096 * 512];   // xT: [b][n][c] fp16
__device__ __align__(16) __half g_wh [655360];             // converted weights
__device__ __align__(16) __half g_h  [4LL * 4096 * 256];   // h:   [n][c]
__device__ __align__(16) __half g_K  [4LL * 4096 * 256];   // Kt:  [n][ck]
__device__ __align__(16) __half g_Q  [4LL * 4096 * 256];   // Qt:  [n][ck]
__device__ __align__(16) __half g_V  [4LL * 256 * 4096];   // V:   [c][n]
__device__ __align__(16) __half g_ctx[4LL * 4096 * 256];   // ctxT:[n][c]
__device__ float               g_S  [4LL * 4096 * 4096];   // logits fp32
__device__ __align__(16) __half g_P  [4LL * 4096 * 4096];  // probs fp16

// weight offsets inside g_wh
#define W_KW1 0
#define W_KW2 131072
#define W_QW1 196608
#define W_QW2 327680
#define W_VW  393216
#define W_OW  524288

// ---------------------------------------------------------------------------
// PTX helpers (all sm_80/75-era -- safe under plain sm_103 ptx target)
// ---------------------------------------------------------------------------
__device__ __forceinline__ uint32_t smem_u32(const void* p) {
    uint32_t a;
    asm("{ .reg .u64 t; cvta.to.shared.u64 t, %1; cvt.u32.u64 %0, t; }" : "=r"(a) : "l"(p));
    return a;
}
#define CP_ASYNC16(dst, src) \
    asm volatile("cp.async.cg.shared.global [%0], [%1], 16;" :: "r"(dst), "l"(src))
#define CP_COMMIT() asm volatile("cp.async.commit_group;" ::: "memory")
#define CP_WAIT2()  asm volatile("cp.async.wait_group 2;"  ::: "memory")

__device__ __forceinline__ void ldsm_x4(uint32_t& r0, uint32_t& r1, uint32_t& r2,
                                        uint32_t& r3, uint32_t addr) {
    asm volatile("ldmatrix.sync.aligned.m8n8.x4.shared.b16 {%0,%1,%2,%3}, [%4];"
                 : "=r"(r0), "=r"(r1), "=r"(r2), "=r"(r3) : "r"(addr));
}
__device__ __forceinline__ void mma_f16(float* d, const uint32_t* a, const uint32_t* b) {
    asm volatile(
        "mma.sync.aligned.m16n8k16.row.col.f32.f16.f16.f32 "
        "{%0,%1,%2,%3}, {%4,%5,%6,%7}, {%8,%9}, {%0,%1,%2,%3};"
        : "+f"(d[0]), "+f"(d[1]), "+f"(d[2]), "+f"(d[3])
        : "r"(a[0]), "r"(a[1]), "r"(a[2]), "r"(a[3]),
          "r"(b[0]), "r"(b[1]));
}

// ---------------------------------------------------------------------------
// Preprocessing: fp32 -> fp16 convert, and transpose-convert of x
// ---------------------------------------------------------------------------
__global__ void f2h_kernel(const float* __restrict__ s, __half* __restrict__ d, int n)
{
    int i = (blockIdx.x * blockDim.x + threadIdx.x) * 4;
    if (i < n) {
        float4 v = *(const float4*)(s + i);
        *(__half2*)(d + i)     = __floats2half2_rn(v.x, v.y);
        *(__half2*)(d + i + 2) = __floats2half2_rn(v.z, v.w);
    }
}

// x [4][512][4096] fp32 -> xT [4][4096][512] fp16
__global__ void xT_kernel(const float* __restrict__ x, __half* __restrict__ xT)
{
    __shared__ float t[32][33];
    const int n0 = blockIdx.x * 32, c0 = blockIdx.y * 32;
    const long long b = blockIdx.z;
    const float* xb = x + (b * 512 + c0) * 4096 + n0;
#pragma unroll
    for (int j = 0; j < 32; j += 8)
        t[threadIdx.y + j][threadIdx.x] = xb[(long long)(threadIdx.y + j) * 4096 + threadIdx.x];
    __syncthreads();
    __half* dst = xT + (b * 4096 + n0) * 512 + c0;
#pragma unroll
    for (int j = 0; j < 32; j += 8)
        dst[(long long)(threadIdx.y + j) * 512 + threadIdx.x] =
            __float2half_rn(t[threadIdx.x][threadIdx.y + j]);
}

// ---------------------------------------------------------------------------
// fp16 GEMM: D[m,n] = epi( sum_k A[m,k]*B[n,k] )
// A fp16 [M][K] (ldA, K contig), B fp16 [N][K] (ldB, K contig).
// CTA 128x128, BK=32, 4-stage cp.async pipeline, ldmatrix fragments.
// 8 warps (2m x 4n), warp tile 64x32.
//  EPI: 0 = *scale; 1 = +bias[m]; 2 = relu((acc+bias[m])*s[m]+t[m])
//  OUT: 0 = fp32 C[m*ldC+n]; 1 = fp16 C[m*ldC+n]; 2 = fp16 C[n*ldC+m]
// SMEM per stage: A 128 rows x 80B + B same = 20480B; 4 stages = 81920B.
// ---------------------------------------------------------------------------
template <int EPI, int OUT>
__global__ void __launch_bounds__(256, 2)
gemm16(const __half* __restrict__ A, long long sAb, int ldA,
       const __half* __restrict__ B, long long sBb, int ldB,
       void* __restrict__ Cv, long long sCb, int ldC,
       int K, float scale,
       const float* __restrict__ bias,
       const float* __restrict__ gam, const float* __restrict__ bet,
       const float* __restrict__ mu,  const float* __restrict__ var)
{
    extern __shared__ char sm[];
    const uint32_t sb = smem_u32(sm);

    const int tid = threadIdx.x, lane = tid & 31, wid = tid >> 5;
    const int wm = wid >> 2, wn = wid & 3;
    const int m0 = blockIdx.y * 128, n0 = blockIdx.x * 128;
    const long long bz = blockIdx.z;

    A += bz * sAb + (long long)m0 * ldA;
    B += bz * sBb + (long long)n0 * ldB;

    const int crow = tid >> 2;        // 0..63
    const int cq   = tid & 3;         // quad within row

    auto issue = [&](int s, int c) {
        const int k0 = c << 5;
        const uint32_t st = sb + s * 20480;
#pragma unroll
        for (int i = 0; i < 2; ++i) {
            const int row = i * 64 + crow;
            CP_ASYNC16(st + row * 80 + cq * 16,
                       A + (long long)row * ldA + k0 + cq * 8);
            CP_ASYNC16(st + 10240 + row * 80 + cq * 16,
                       B + (long long)row * ldB + k0 + cq * 8);
        }
    };

    float acc[4][4][4];
#pragma unroll
    for (int i = 0; i < 4; ++i)
#pragma unroll
        for (int j = 0; j < 4; ++j)
#pragma unroll
            for (int r = 0; r < 4; ++r) acc[i][j][r] = 0.f;

    const int NCH = K >> 5;

    issue(0, 0); CP_COMMIT();
    issue(1, 1); CP_COMMIT();
    issue(2, 2); CP_COMMIT();

    // fragment smem offsets (stage-invariant parts)
    const uint32_t aoff = (wm * 64 + (lane & 15)) * 80 + (lane >> 4) * 16;
    const uint32_t boff = 10240 + (wn * 32 + (lane & 7) + ((lane >> 4) << 3)) * 80
                        + ((lane >> 3) & 1) * 16;

    for (int c = 0; c < NCH; ++c) {
        CP_WAIT2();
        __syncthreads();
        const uint32_t st = sb + (c & 3) * 20480;

        uint32_t a0[4][4], b0[4][2];
        // ---- kstep 0 loads ----
#pragma unroll
        for (int i = 0; i < 4; ++i)
            ldsm_x4(a0[i][0], a0[i][1], a0[i][2], a0[i][3],
                    st + aoff + i * (16 * 80));
#pragma unroll
        for (int p = 0; p < 2; ++p) {
            uint32_t t0, t1, t2, t3;
            ldsm_x4(t0, t1, t2, t3, st + boff + p * (16 * 80));
            b0[2 * p][0] = t0; b0[2 * p][1] = t1;
            b0[2 * p + 1][0] = t2; b0[2 * p + 1][1] = t3;
        }

        // ---- prefetch next stage ----
        if (c + 3 < NCH) issue((c + 3) & 3, c + 3);
        CP_COMMIT();

        // ---- kstep 0 mma ----
#pragma unroll
        for (int i = 0; i < 4; ++i)
#pragma unroll
            for (int j = 0; j < 4; ++j)
                mma_f16(acc[i][j], a0[i], b0[j]);

        // ---- kstep 1 loads + mma ----
        uint32_t a1[4][4], b1[4][2];
#pragma unroll
        for (int i = 0; i < 4; ++i)
            ldsm_x4(a1[i][0], a1[i][1], a1[i][2], a1[i][3],
                    st + aoff + i * (16 * 80) + 32);
#pragma unroll
        for (int p = 0; p < 2; ++p) {
            uint32_t t0, t1, t2, t3;
            ldsm_x4(t0, t1, t2, t3, st + boff + p * (16 * 80) + 32);
            b1[2 * p][0] = t0; b1[2 * p][1] = t1;
            b1[2 * p + 1][0] = t2; b1[2 * p + 1][1] = t3;
        }
#pragma unroll
        for (int i = 0; i < 4; ++i)
#pragma unroll
            for (int j = 0; j < 4; ++j)
                mma_f16(acc[i][j], a1[i], b1[j]);
    }

    // ---- epilogue ----
    float*  CgF = (float*) Cv + bz * sCb;
    __half* CgH = (__half*)Cv + bz * sCb;
    const int g = lane >> 2, q4 = lane & 3;
#pragma unroll
    for (int i = 0; i < 4; ++i) {
        const int mA = m0 + wm * 64 + i * 16 + g;
        const int mB = mA + 8;
        float bA = 0.f, bB = 0.f, sA = 1.f, sB = 1.f, tA = 0.f, tB = 0.f;
        if (EPI >= 1) { bA = bias[mA]; bB = bias[mB]; }
        if (EPI == 2) {
            sA = gam[mA] * rsqrtf(var[mA] + EPSV); tA = bet[mA] - mu[mA] * sA;
            sB = gam[mB] * rsqrtf(var[mB] + EPSV); tB = bet[mB] - mu[mB] * sB;
        }
#pragma unroll
        for (int j = 0; j < 4; ++j) {
            const int col = n0 + wn * 32 + j * 8 + q4 * 2;
            float v00 = acc[i][j][0], v01 = acc[i][j][1];
            float v10 = acc[i][j][2], v11 = acc[i][j][3];
            if (EPI == 0) { v00 *= scale; v01 *= scale; v10 *= scale; v11 *= scale; }
            if (EPI == 1) { v00 += bA; v01 += bA; v10 += bB; v11 += bB; }
            if (EPI == 2) {
                v00 = fmaxf(fmaf(v00 + bA, sA, tA), 0.f);
                v01 = fmaxf(fmaf(v01 + bA, sA, tA), 0.f);
                v10 = fmaxf(fmaf(v10 + bB, sB, tB), 0.f);
                v11 = fmaxf(fmaf(v11 + bB, sB, tB), 0.f);
            }
            if (OUT == 0) {
                *(float2*)&CgF[(long long)mA * ldC + col] = make_float2(v00, v01);
                *(float2*)&CgF[(long long)mB * ldC + col] = make_float2(v10, v11);
            } else if (OUT == 1) {
                *(__half2*)&CgH[(long long)mA * ldC + col] = __floats2half2_rn(v00, v01);
                *(__half2*)&CgH[(long long)mB * ldC + col] = __floats2half2_rn(v10, v11);
            } else {
                CgH[(long long)col * ldC + mA]       = __float2half_rn(v00);
                CgH[(long long)(col + 1) * ldC + mA] = __float2half_rn(v01);
                CgH[(long long)col * ldC + mB]       = __float2half_rn(v10);
                CgH[(long long)(col + 1) * ldC + mB] = __float2half_rn(v11);
            }
        }
    }
}

// ---------------------------------------------------------------------------
// Row softmax: S fp32 [row][4096] -> P fp16, one 256-thread block per row.
// ---------------------------------------------------------------------------
__global__ void __launch_bounds__(256)
softmax_kernel(const float* __restrict__ S, __half* __restrict__ P)
{
    const int N = 4096;
    const float* p = S + (long long)blockIdx.x * N;
    __half* po = P + (long long)blockIdx.x * N;
    const int tid = threadIdx.x;

    float4 v[4];
    float mx = -3.4e38f;
#pragma unroll
    for (int i = 0; i < 4; i++) {
        v[i] = *(const float4*)&p[i * 1024 + tid * 4];
        mx = fmaxf(mx, fmaxf(fmaxf(v[i].x, v[i].y), fmaxf(v[i].z, v[i].w)));
    }

    __shared__ float redA[8];
    __shared__ float redB[8];
#pragma unroll
    for (int o = 16; o; o >>= 1)
        mx = fmaxf(mx, __shfl_xor_sync(0xffffffffu, mx, o));
    if ((tid & 31) == 0) redA[tid >> 5] = mx;
    __syncthreads();
#pragma unroll
    for (int w = 0; w < 8; w++) mx = fmaxf(mx, redA[w]);

    float sum = 0.f;
#pragma unroll
    for (int i = 0; i < 4; i++) {
        v[i].x = __expf(v[i].x - mx);
        v[i].y = __expf(v[i].y - mx);
        v[i].z = __expf(v[i].z - mx);
        v[i].w = __expf(v[i].w - mx);
        sum += v[i].x + v[i].y + v[i].z + v[i].w;
    }
#pragma unroll
    for (int o = 16; o; o >>= 1)
        sum += __shfl_xor_sync(0xffffffffu, sum, o);
    if ((tid & 31) == 0) redB[tid >> 5] = sum;
    __syncthreads();
    sum = 0.f;
#pragma unroll
    for (int w = 0; w < 8; w++) sum += redB[w];

    const float inv = 1.f / sum;
#pragma unroll
    for (int i = 0; i < 4; i++) {
        __half2* q = (__half2*)&po[i * 1024 + tid * 4];
        q[0] = __floats2half2_rn(v[i].x * inv, v[i].y * inv);
        q[1] = __floats2half2_rn(v[i].z * inv, v[i].w * inv);
    }
}

// ---------------------------------------------------------------------------
extern "C" void kernel_launch(void* const* d_in, const int* in_sizes, int n_in,
                              void* d_out, int out_size)
{
    const float* x     = (const float*)d_in[0];
    const float* k_w1  = (const float*)d_in[1];
    const float* k_b1  = (const float*)d_in[2];
    const float* k_g1  = (const float*)d_in[3];
    const float* k_be1 = (const float*)d_in[4];
    const float* k_m1  = (const float*)d_in[5];
    const float* k_v1  = (const float*)d_in[6];
    const float* k_w2  = (const float*)d_in[7];
    const float* k_b2  = (const float*)d_in[8];
    const float* k_g2  = (const float*)d_in[9];
    const float* k_be2 = (const float*)d_in[10];
    const float* k_m2  = (const float*)d_in[11];
    const float* k_v2  = (const float*)d_in[12];
    const float* q_w1  = (const float*)d_in[13];
    const float* q_b1  = (const float*)d_in[14];
    const float* q_g1  = (const float*)d_in[15];
    const float* q_be1 = (const float*)d_in[16];
    const float* q_m1  = (const float*)d_in[17];
    const float* q_v1  = (const float*)d_in[18];
    const float* q_w2  = (const float*)d_in[19];
    const float* q_b2  = (const float*)d_in[20];
    const float* q_g2  = (const float*)d_in[21];
    const float* q_be2 = (const float*)d_in[22];
    const float* q_m2  = (const float*)d_in[23];
    const float* q_v2  = (const float*)d_in[24];
    const float* v_w   = (const float*)d_in[25];
    const float* v_b   = (const float*)d_in[26];
    const float* o_w   = (const float*)d_in[27];
    const float* o_b   = (const float*)d_in[28];

    void *xT_, *wh_, *h_, *Kt_, *Qt_, *V_, *S_, *P_, *ctx_;
    cudaGetSymbolAddress(&xT_,  g_xT);
    cudaGetSymbolAddress(&wh_,  g_wh);
    cudaGetSymbolAddress(&h_,   g_h);
    cudaGetSymbolAddress(&Kt_,  g_K);
    cudaGetSymbolAddress(&Qt_,  g_Q);
    cudaGetSymbolAddress(&V_,   g_V);
    cudaGetSymbolAddress(&S_,   g_S);
    cudaGetSymbolAddress(&P_,   g_P);
    cudaGetSymbolAddress(&ctx_, g_ctx);
    __half* xT  = (__half*)xT_;
    __half* wh  = (__half*)wh_;
    __half* h   = (__half*)h_;
    __half* Kt  = (__half*)Kt_;
    __half* Qt  = (__half*)Qt_;
    __half* V   = (__half*)V_;
    float*  S   = (float*)S_;
    __half* P   = (__half*)P_;
    __half* ctx = (__half*)ctx_;

    const long long sXT = 4096LL * 512;
    const long long sC  = 4096LL * 256;
    const long long sS  = 4096LL * 4096;
    const long long sO  = 512LL * 4096;

    const int GSM = 81920;
    cudaFuncSetAttribute(gemm16<2,2>, cudaFuncAttributeMaxDynamicSharedMemorySize, GSM);
    cudaFuncSetAttribute(gemm16<1,1>, cudaFuncAttributeMaxDynamicSharedMemorySize, GSM);
    cudaFuncSetAttribute(gemm16<0,0>, cudaFuncAttributeMaxDynamicSharedMemorySize, GSM);
    cudaFuncSetAttribute(gemm16<0,2>, cudaFuncAttributeMaxDynamicSharedMemorySize, GSM);
    cudaFuncSetAttribute(gemm16<1,0>, cudaFuncAttributeMaxDynamicSharedMemorySize, GSM);

    // ---- preprocessing ----
    f2h_kernel<<<128, 256>>>(k_w1, wh + W_KW1, 131072);
    f2h_kernel<<< 64, 256>>>(k_w2, wh + W_KW2,  65536);
    f2h_kernel<<<128, 256>>>(q_w1, wh + W_QW1, 131072);
    f2h_kernel<<< 64, 256>>>(q_w2, wh + W_QW2,  65536);
    f2h_kernel<<<128, 256>>>(v_w,  wh + W_VW,  131072);
    f2h_kernel<<<128, 256>>>(o_w,  wh + W_OW,  131072);
    xT_kernel<<<dim3(128, 16, 4), dim3(32, 8)>>>(x, xT);

    const dim3 gProj(32, 2, 4);   // M=256
    const dim3 gOut (32, 4, 4);   // M=512
    const dim3 gSim (32, 32, 4);

    // ---- k branch: h[n][c] = relu(bn(W1 x)); Kt[n][ck] = relu(bn(W2 h)) ----
    gemm16<2,2><<<gProj, 256, GSM>>>(wh + W_KW1, 0, 512, xT, sXT, 512, h, sC, 256,
                                     512, 0.f, k_b1, k_g1, k_be1, k_m1, k_v1);
    gemm16<2,2><<<gProj, 256, GSM>>>(wh + W_KW2, 0, 256, h, sC, 256, Kt, sC, 256,
                                     256, 0.f, k_b2, k_g2, k_be2, k_m2, k_v2);
    // ---- q branch ----
    gemm16<2,2><<<gProj, 256, GSM>>>(wh + W_QW1, 0, 512, xT, sXT, 512, h, sC, 256,
                                     512, 0.f, q_b1, q_g1, q_be1, q_m1, q_v1);
    gemm16<2,2><<<gProj, 256, GSM>>>(wh + W_QW2, 0, 256, h, sC, 256, Qt, sC, 256,
                                     256, 0.f, q_b2, q_g2, q_be2, q_m2, q_v2);
    // ---- value: V[c][n] ----
    gemm16<1,1><<<gProj, 256, GSM>>>(wh + W_VW, 0, 512, xT, sXT, 512, V, sC, 4096,
                                     512, 0.f, v_b, nullptr, nullptr, nullptr, nullptr);
    // ---- sim[nq][nk] = 0.0625 * <Qt[nq,:], Kt[nk,:]> (fp32 out) ----
    gemm16<0,0><<<gSim, 256, GSM>>>(Qt, sC, 256, Kt, sC, 256, S, sS, 4096,
                                    256, 0.0625f, nullptr, nullptr, nullptr, nullptr, nullptr);
    // ---- softmax over keys ----
    softmax_kernel<<<4 * 4096, 256>>>(S, P);
    // ---- ctxT[nq][c] = sum_key V[c,key] * P[nq,key] ----
    gemm16<0,2><<<gProj, 256, GSM>>>(V, sC, 4096, P, sS, 4096, ctx, sC, 256,
                                     4096, 1.0f, nullptr, nullptr, nullptr, nullptr, nullptr);
    // ---- out[co][n] = o_w @ ctx + o_b (fp32) ----
    gemm16<1,0><<<gOut, 256, GSM>>>(wh + W_OW, 0, 256, ctx, sC, 256, d_out, sO, 4096,
                                    256, 0.f, o_b, nullptr, nullptr, nullptr, nullptr);
}

// round 8
// speedup vs baseline: 2.0795x; 1.1586x over previous
#include <cuda_runtime.h>
#include <cuda_fp16.h>
#include <cstdint>

#define EPSV 1e-5f

// ---------------------------------------------------------------------------
// Scratch
// ---------------------------------------------------------------------------
__device__ __align__(16) __half g_xT [4LL * 4096 * 512];   // xT: [b][n][c] fp16
__device__ __align__(16) __half g_wh [655360];             // converted weights
__device__ __align__(16) __half g_h  [4LL * 4096 * 256];   // h:   [n][c]
__device__ __align__(16) __half g_K  [4LL * 4096 * 256];   // Kt:  [n][ck]
__device__ __align__(16) __half g_Q  [4LL * 4096 * 256];   // Qt:  [n][ck]
__device__ __align__(16) __half g_V  [4LL * 256 * 4096];   // V:   [c][n]
__device__ __align__(16) __half g_ctx[4LL * 4096 * 256];   // ctxT:[n][c]
__device__ __align__(16) __half g_P  [4LL * 4096 * 4096];  // unnormalized probs fp16
__device__ float               g_l  [4LL * 4096];          // softmax row sums

// weight offsets inside g_wh
#define W_KW1 0
#define W_KW2 131072
#define W_QW1 196608
#define W_QW2 327680
#define W_VW  393216
#define W_OW  524288

// ---------------------------------------------------------------------------
// PTX helpers
// ---------------------------------------------------------------------------
__device__ __forceinline__ uint32_t smem_u32(const void* p) {
    uint32_t a;
    asm("{ .reg .u64 t; cvta.to.shared.u64 t, %1; cvt.u32.u64 %0, t; }" : "=r"(a) : "l"(p));
    return a;
}
#define CP_ASYNC16(dst, src) \
    asm volatile("cp.async.cg.shared.global [%0], [%1], 16;" :: "r"(dst), "l"(src))
#define CP_COMMIT() asm volatile("cp.async.commit_group;" ::: "memory")
#define CP_WAIT2()  asm volatile("cp.async.wait_group 2;"  ::: "memory")

__device__ __forceinline__ void ldsm_x4(uint32_t& r0, uint32_t& r1, uint32_t& r2,
                                        uint32_t& r3, uint32_t addr) {
    asm volatile("ldmatrix.sync.aligned.m8n8.x4.shared.b16 {%0,%1,%2,%3}, [%4];"
                 : "=r"(r0), "=r"(r1), "=r"(r2), "=r"(r3) : "r"(addr));
}
__device__ __forceinline__ void mma_f16(float* d, const uint32_t* a, const uint32_t* b) {
    asm volatile(
        "mma.sync.aligned.m16n8k16.row.col.f32.f16.f16.f32 "
        "{%0,%1,%2,%3}, {%4,%5,%6,%7}, {%8,%9}, {%0,%1,%2,%3};"
        : "+f"(d[0]), "+f"(d[1]), "+f"(d[2]), "+f"(d[3])
        : "r"(a[0]), "r"(a[1]), "r"(a[2]), "r"(a[3]),
          "r"(b[0]), "r"(b[1]));
}

// ---------------------------------------------------------------------------
// Preprocessing
// ---------------------------------------------------------------------------
// All six weight matrices fp32 -> fp16 in ONE kernel (segment table by offset).
__global__ void wconv_kernel(const float* __restrict__ kw1, const float* __restrict__ kw2,
                             const float* __restrict__ qw1, const float* __restrict__ qw2,
                             const float* __restrict__ vw,  const float* __restrict__ ow,
                             __half* __restrict__ d)
{
    int i = (blockIdx.x * blockDim.x + threadIdx.x) * 4;
    if (i >= 655360) return;
    const float* s; int off;
    if      (i < W_KW2) { s = kw1; off = i - W_KW1; }
    else if (i < W_QW1) { s = kw2; off = i - W_KW2; }
    else if (i < W_QW2) { s = qw1; off = i - W_QW1; }
    else if (i < W_VW ) { s = qw2; off = i - W_QW2; }
    else if (i < W_OW ) { s = vw;  off = i - W_VW;  }
    else                { s = ow;  off = i - W_OW;  }
    float4 v = *(const float4*)(s + off);
    *(__half2*)(d + i)     = __floats2half2_rn(v.x, v.y);
    *(__half2*)(d + i + 2) = __floats2half2_rn(v.z, v.w);
}

__global__ void zero_l_kernel(float* __restrict__ l)
{
    l[blockIdx.x * 1024 + threadIdx.x] = 0.f;
}

// x [4][512][4096] fp32 -> xT [4][4096][512] fp16
__global__ void xT_kernel(const float* __restrict__ x, __half* __restrict__ xT)
{
    __shared__ float t[32][33];
    const int n0 = blockIdx.x * 32, c0 = blockIdx.y * 32;
    const long long b = blockIdx.z;
    const float* xb = x + (b * 512 + c0) * 4096 + n0;
#pragma unroll
    for (int j = 0; j < 32; j += 8)
        t[threadIdx.y + j][threadIdx.x] = xb[(long long)(threadIdx.y + j) * 4096 + threadIdx.x];
    __syncthreads();
    __half* dst = xT + (b * 4096 + n0) * 512 + c0;
#pragma unroll
    for (int j = 0; j < 32; j += 8)
        dst[(long long)(threadIdx.y + j) * 512 + threadIdx.x] =
            __float2half_rn(t[threadIdx.x][threadIdx.y + j]);
}

// ---------------------------------------------------------------------------
// fp16 GEMM: D[m,n] = epi( sum_k A[m,k]*B[n,k] )
// A fp16 [M][K] (ldA, K contig), B fp16 [N][K] (ldB, K contig).
// CTA 128x128, BK=32, 4-stage cp.async pipeline, ldmatrix fragments.
//  EPI: 0 = *scale
//       1 = +bias[m]
//       2 = relu((acc+bias[m])*s[m]+t[m])
//       3 = * (1 / aux[col])            (column-wise softmax normalization)
//       4 = exp(acc*scale - 3), row sums atomically added into aux[row]
//  OUT: 0 = fp32 C[m*ldC+n]; 1 = fp16 C[m*ldC+n]; 2 = fp16 C[n*ldC+m]
// ---------------------------------------------------------------------------
template <int EPI, int OUT>
__global__ void __launch_bounds__(256, 2)
gemm16(const __half* __restrict__ A, long long sAb, int ldA,
       const __half* __restrict__ B, long long sBb, int ldB,
       void* __restrict__ Cv, long long sCb, int ldC,
       int K, float scale,
       const float* __restrict__ bias,
       const float* __restrict__ gam, const float* __restrict__ bet,
       const float* __restrict__ mu,  const float* __restrict__ var,
       float* __restrict__ aux)
{
    extern __shared__ char sm[];
    const uint32_t sb = smem_u32(sm);

    const int tid = threadIdx.x, lane = tid & 31, wid = tid >> 5;
    const int wm = wid >> 2, wn = wid & 3;
    const int m0 = blockIdx.y * 128, n0 = blockIdx.x * 128;
    const long long bz = blockIdx.z;

    A += bz * sAb + (long long)m0 * ldA;
    B += bz * sBb + (long long)n0 * ldB;

    const int crow = tid >> 2;
    const int cq   = tid & 3;

    auto issue = [&](int s, int c) {
        const int k0 = c << 5;
        const uint32_t st = sb + s * 20480;
#pragma unroll
        for (int i = 0; i < 2; ++i) {
            const int row = i * 64 + crow;
            CP_ASYNC16(st + row * 80 + cq * 16,
                       A + (long long)row * ldA + k0 + cq * 8);
            CP_ASYNC16(st + 10240 + row * 80 + cq * 16,
                       B + (long long)row * ldB + k0 + cq * 8);
        }
    };

    float acc[4][4][4];
#pragma unroll
    for (int i = 0; i < 4; ++i)
#pragma unroll
        for (int j = 0; j < 4; ++j)
#pragma unroll
            for (int r = 0; r < 4; ++r) acc[i][j][r] = 0.f;

    const int NCH = K >> 5;

    issue(0, 0); CP_COMMIT();
    issue(1, 1); CP_COMMIT();
    issue(2, 2); CP_COMMIT();

    const uint32_t aoff = (wm * 64 + (lane & 15)) * 80 + (lane >> 4) * 16;
    const uint32_t boff = 10240 + (wn * 32 + (lane & 7) + ((lane >> 4) << 3)) * 80
                        + ((lane >> 3) & 1) * 16;

    for (int c = 0; c < NCH; ++c) {
        CP_WAIT2();
        __syncthreads();
        const uint32_t st = sb + (c & 3) * 20480;

        uint32_t a0[4][4], b0[4][2];
#pragma unroll
        for (int i = 0; i < 4; ++i)
            ldsm_x4(a0[i][0], a0[i][1], a0[i][2], a0[i][3],
                    st + aoff + i * (16 * 80));
#pragma unroll
        for (int p = 0; p < 2; ++p) {
            uint32_t t0, t1, t2, t3;
            ldsm_x4(t0, t1, t2, t3, st + boff + p * (16 * 80));
            b0[2 * p][0] = t0; b0[2 * p][1] = t1;
            b0[2 * p + 1][0] = t2; b0[2 * p + 1][1] = t3;
        }

        if (c + 3 < NCH) issue((c + 3) & 3, c + 3);
        CP_COMMIT();

#pragma unroll
        for (int i = 0; i < 4; ++i)
#pragma unroll
            for (int j = 0; j < 4; ++j)
                mma_f16(acc[i][j], a0[i], b0[j]);

        uint32_t a1[4][4], b1[4][2];
#pragma unroll
        for (int i = 0; i < 4; ++i)
            ldsm_x4(a1[i][0], a1[i][1], a1[i][2], a1[i][3],
                    st + aoff + i * (16 * 80) + 32);
#pragma unroll
        for (int p = 0; p < 2; ++p) {
            uint32_t t0, t1, t2, t3;
            ldsm_x4(t0, t1, t2, t3, st + boff + p * (16 * 80) + 32);
            b1[2 * p][0] = t0; b1[2 * p][1] = t1;
            b1[2 * p + 1][0] = t2; b1[2 * p + 1][1] = t3;
        }
#pragma unroll
        for (int i = 0; i < 4; ++i)
#pragma unroll
            for (int j = 0; j < 4; ++j)
                mma_f16(acc[i][j], a1[i], b1[j]);
    }

    // ---- epilogue ----
    float*  CgF = (float*) Cv + bz * sCb;
    __half* CgH = (__half*)Cv + bz * sCb;
    const int g = lane >> 2, q4 = lane & 3;

    if (EPI == 4) {
        // exp + unnormalized fp16 store + atomic row sums (OUT must be 1)
        float* lsum = aux + bz * 4096;
#pragma unroll
        for (int i = 0; i < 4; ++i) {
            const int mA = m0 + wm * 64 + i * 16 + g;
            const int mB = mA + 8;
            float sA = 0.f, sB = 0.f;
#pragma unroll
            for (int j = 0; j < 4; ++j) {
                const int col = n0 + wn * 32 + j * 8 + q4 * 2;
                float v00 = __expf(fmaf(acc[i][j][0], scale, -3.f));
                float v01 = __expf(fmaf(acc[i][j][1], scale, -3.f));
                float v10 = __expf(fmaf(acc[i][j][2], scale, -3.f));
                float v11 = __expf(fmaf(acc[i][j][3], scale, -3.f));
                sA += v00 + v01; sB += v10 + v11;
                *(__half2*)&CgH[(long long)mA * ldC + col] = __floats2half2_rn(v00, v01);
                *(__half2*)&CgH[(long long)mB * ldC + col] = __floats2half2_rn(v10, v11);
            }
            sA += __shfl_xor_sync(0xffffffffu, sA, 1);
            sA += __shfl_xor_sync(0xffffffffu, sA, 2);
            sB += __shfl_xor_sync(0xffffffffu, sB, 1);
            sB += __shfl_xor_sync(0xffffffffu, sB, 2);
            if (q4 == 0) {
                atomicAdd(&lsum[mA], sA);
                atomicAdd(&lsum[mB], sB);
            }
        }
        return;
    }

    float cs0[4], cs1[4];
    if (EPI == 3) {
        const float* ls = aux + bz * 4096;
#pragma unroll
        for (int j = 0; j < 4; ++j) {
            const int col = n0 + wn * 32 + j * 8 + q4 * 2;
            cs0[j] = 1.f / ls[col];
            cs1[j] = 1.f / ls[col + 1];
        }
    }

#pragma unroll
    for (int i = 0; i < 4; ++i) {
        const int mA = m0 + wm * 64 + i * 16 + g;
        const int mB = mA + 8;
        float bA = 0.f, bB = 0.f, sA = 1.f, sB = 1.f, tA = 0.f, tB = 0.f;
        if (EPI == 1 || EPI == 2) { bA = bias[mA]; bB = bias[mB]; }
        if (EPI == 2) {
            sA = gam[mA] * rsqrtf(var[mA] + EPSV); tA = bet[mA] - mu[mA] * sA;
            sB = gam[mB] * rsqrtf(var[mB] + EPSV); tB = bet[mB] - mu[mB] * sB;
        }
#pragma unroll
        for (int j = 0; j < 4; ++j) {
            const int col = n0 + wn * 32 + j * 8 + q4 * 2;
            float v00 = acc[i][j][0], v01 = acc[i][j][1];
            float v10 = acc[i][j][2], v11 = acc[i][j][3];
            if (EPI == 0) { v00 *= scale; v01 *= scale; v10 *= scale; v11 *= scale; }
            if (EPI == 1) { v00 += bA; v01 += bA; v10 += bB; v11 += bB; }
            if (EPI == 2) {
                v00 = fmaxf(fmaf(v00 + bA, sA, tA), 0.f);
                v01 = fmaxf(fmaf(v01 + bA, sA, tA), 0.f);
                v10 = fmaxf(fmaf(v10 + bB, sB, tB), 0.f);
                v11 = fmaxf(fmaf(v11 + bB, sB, tB), 0.f);
            }
            if (EPI == 3) {
                v00 *= cs0[j]; v01 *= cs1[j];
                v10 *= cs0[j]; v11 *= cs1[j];
            }
            if (OUT == 0) {
                *(float2*)&CgF[(long long)mA * ldC + col] = make_float2(v00, v01);
                *(float2*)&CgF[(long long)mB * ldC + col] = make_float2(v10, v11);
            } else if (OUT == 1) {
                *(__half2*)&CgH[(long long)mA * ldC + col] = __floats2half2_rn(v00, v01);
                *(__half2*)&CgH[(long long)mB * ldC + col] = __floats2half2_rn(v10, v11);
            } else {
                CgH[(long long)col * ldC + mA]       = __float2half_rn(v00);
                CgH[(long long)(col + 1) * ldC + mA] = __float2half_rn(v01);
                CgH[(long long)col * ldC + mB]       = __float2half_rn(v10);
                CgH[(long long)(col + 1) * ldC + mB] = __float2half_rn(v11);
            }
        }
    }
}

// ---------------------------------------------------------------------------
extern "C" void kernel_launch(void* const* d_in, const int* in_sizes, int n_in,
                              void* d_out, int out_size)
{
    const float* x     = (const float*)d_in[0];
    const float* k_w1  = (const float*)d_in[1];
    const float* k_b1  = (const float*)d_in[2];
    const float* k_g1  = (const float*)d_in[3];
    const float* k_be1 = (const float*)d_in[4];
    const float* k_m1  = (const float*)d_in[5];
    const float* k_v1  = (const float*)d_in[6];
    const float* k_w2  = (const float*)d_in[7];
    const float* k_b2  = (const float*)d_in[8];
    const float* k_g2  = (const float*)d_in[9];
    const float* k_be2 = (const float*)d_in[10];
    const float* k_m2  = (const float*)d_in[11];
    const float* k_v2  = (const float*)d_in[12];
    const float* q_w1  = (const float*)d_in[13];
    const float* q_b1  = (const float*)d_in[14];
    const float* q_g1  = (const float*)d_in[15];
    const float* q_be1 = (const float*)d_in[16];
    const float* q_m1  = (const float*)d_in[17];
    const float* q_v1  = (const float*)d_in[18];
    const float* q_w2  = (const float*)d_in[19];
    const float* q_b2  = (const float*)d_in[20];
    const float* q_g2  = (const float*)d_in[21];
    const float* q_be2 = (const float*)d_in[22];
    const float* q_m2  = (const float*)d_in[23];
    const float* q_v2  = (const float*)d_in[24];
    const float* v_w   = (const float*)d_in[25];
    const float* v_b   = (const float*)d_in[26];
    const float* o_w   = (const float*)d_in[27];
    const float* o_b   = (const float*)d_in[28];

    void *xT_, *wh_, *h_, *Kt_, *Qt_, *V_, *P_, *ctx_, *l_;
    cudaGetSymbolAddress(&xT_,  g_xT);
    cudaGetSymbolAddress(&wh_,  g_wh);
    cudaGetSymbolAddress(&h_,   g_h);
    cudaGetSymbolAddress(&Kt_,  g_K);
    cudaGetSymbolAddress(&Qt_,  g_Q);
    cudaGetSymbolAddress(&V_,   g_V);
    cudaGetSymbolAddress(&P_,   g_P);
    cudaGetSymbolAddress(&ctx_, g_ctx);
    cudaGetSymbolAddress(&l_,   g_l);
    __half* xT  = (__half*)xT_;
    __half* wh  = (__half*)wh_;
    __half* h   = (__half*)h_;
    __half* Kt  = (__half*)Kt_;
    __half* Qt  = (__half*)Qt_;
    __half* V   = (__half*)V_;
    __half* P   = (__half*)P_;
    __half* ctx = (__half*)ctx_;
    float*  lsum = (float*)l_;

    const long long sXT = 4096LL * 512;
    const long long sC  = 4096LL * 256;
    const long long sS  = 4096LL * 4096;
    const long long sO  = 512LL * 4096;

    const int GSM = 81920;
    cudaFuncSetAttribute(gemm16<2,2>, cudaFuncAttributeMaxDynamicSharedMemorySize, GSM);
    cudaFuncSetAttribute(gemm16<1,1>, cudaFuncAttributeMaxDynamicSharedMemorySize, GSM);
    cudaFuncSetAttribute(gemm16<4,1>, cudaFuncAttributeMaxDynamicSharedMemorySize, GSM);
    cudaFuncSetAttribute(gemm16<3,2>, cudaFuncAttributeMaxDynamicSharedMemorySize, GSM);
    cudaFuncSetAttribute(gemm16<1,0>, cudaFuncAttributeMaxDynamicSharedMemorySize, GSM);

    // ---- preprocessing ----
    wconv_kernel<<<640, 256>>>(k_w1, k_w2, q_w1, q_w2, v_w, o_w, wh);
    xT_kernel<<<dim3(128, 16, 4), dim3(32, 8)>>>(x, xT);
    zero_l_kernel<<<16, 1024>>>(lsum);

    const dim3 gProj(32, 2, 4);   // M=256
    const dim3 gOut (32, 4, 4);   // M=512
    const dim3 gSim (32, 32, 4);

    // ---- k branch: h[n][c] = relu(bn(W1 x)); Kt[n][ck] = relu(bn(W2 h)) ----
    gemm16<2,2><<<gProj, 256, GSM>>>(wh + W_KW1, 0, 512, xT, sXT, 512, h, sC, 256,
                                     512, 0.f, k_b1, k_g1, k_be1, k_m1, k_v1, nullptr);
    gemm16<2,2><<<gProj, 256, GSM>>>(wh + W_KW2, 0, 256, h, sC, 256, Kt, sC, 256,
                                     256, 0.f, k_b2, k_g2, k_be2, k_m2, k_v2, nullptr);
    // ---- q branch ----
    gemm16<2,2><<<gProj, 256, GSM>>>(wh + W_QW1, 0, 512, xT, sXT, 512, h, sC, 256,
                                     512, 0.f, q_b1, q_g1, q_be1, q_m1, q_v1, nullptr);
    gemm16<2,2><<<gProj, 256, GSM>>>(wh + W_QW2, 0, 256, h, sC, 256, Qt, sC, 256,
                                     256, 0.f, q_b2, q_g2, q_be2, q_m2, q_v2, nullptr);
    // ---- value: V[c][n] ----
    gemm16<1,1><<<gProj, 256, GSM>>>(wh + W_VW, 0, 512, xT, sXT, 512, V, sC, 4096,
                                     512, 0.f, v_b, nullptr, nullptr, nullptr, nullptr, nullptr);
    // ---- P_unnorm[q][k] = exp(0.0625*<Qt[q],Kt[k]> - 3), row sums -> lsum ----
    gemm16<4,1><<<gSim, 256, GSM>>>(Qt, sC, 256, Kt, sC, 256, P, sS, 4096,
                                    256, 0.0625f, nullptr, nullptr, nullptr, nullptr, nullptr,
                                    lsum);
    // ---- ctxT[q][c] = (sum_key V[c,key] * P[q,key]) / lsum[q] ----
    gemm16<3,2><<<gProj, 256, GSM>>>(V, sC, 4096, P, sS, 4096, ctx, sC, 256,
                                     4096, 1.0f, nullptr, nullptr, nullptr, nullptr, nullptr,
                                     lsum);
    // ---- out[co][n] = o_w @ ctx + o_b (fp32) ----
    gemm16<1,0><<<gOut, 256, GSM>>>(wh + W_OW, 0, 256, ctx, sC, 256, d_out, sO, 4096,
                                    256, 0.f, o_b, nullptr, nullptr, nullptr, nullptr, nullptr);
}